// round 15
// baseline (speedup 1.0000x reference)
#include <cuda_runtime.h>
#include <cuda_bf16.h>
#include <cstdint>
#include <cstddef>

// ---------------------------------------------------------------------------
// Problem constants
// ---------------------------------------------------------------------------
#define NB   16
#define NH   64
#define NW   64
#define NC   512
#define NIC  64
#define NROWS (NB*NH*NW)          // 65536
#define LN_EPS 1e-3f

// Scratch (device globals = sanctioned no-alloc scratch)
__device__ float d_G [(size_t)NROWS * NIC];
__device__ float d_Hs[(size_t)NROWS * NIC];
__device__ __nv_bfloat16 d_Phi[(size_t)NROWS * NIC];
__device__ __nv_bfloat16 d_Plo[(size_t)NROWS * NIC];
// Pre-split weights: [wf|wh] as [512][128], w_fgh as [64][512]
__device__ __nv_bfloat16 d_WH[512 * 128];
__device__ __nv_bfloat16 d_WL[512 * 128];
__device__ __nv_bfloat16 d_FH[64 * 512];
__device__ __nv_bfloat16 d_FL[64 * 512];

// ---------------------------------------------------------------------------
// Helpers (sm_80-family tensor path: mma.sync + ldmatrix + cp.async)
// ---------------------------------------------------------------------------
__device__ __forceinline__ uint32_t smem_u32(const void* p) {
    uint32_t a;
    asm("{ .reg .u64 t; cvta.to.shared.u64 t, %1; cvt.u32.u64 %0, t; }"
        : "=r"(a) : "l"(p));
    return a;
}
__device__ __forceinline__ void ldsm4(uint32_t r[4], uint32_t a) {
    asm volatile("ldmatrix.sync.aligned.m8n8.x4.shared.b16 {%0,%1,%2,%3}, [%4];"
                 : "=r"(r[0]), "=r"(r[1]), "=r"(r[2]), "=r"(r[3]) : "r"(a));
}
__device__ __forceinline__ void ldsm4t(uint32_t r[4], uint32_t a) {
    asm volatile("ldmatrix.sync.aligned.m8n8.x4.trans.shared.b16 {%0,%1,%2,%3}, [%4];"
                 : "=r"(r[0]), "=r"(r[1]), "=r"(r[2]), "=r"(r[3]) : "r"(a));
}
__device__ __forceinline__ void mma16816(float c[4], const uint32_t a[4],
                                         uint32_t b0, uint32_t b1) {
    asm volatile(
        "mma.sync.aligned.m16n8k16.row.col.f32.bf16.bf16.f32 "
        "{%0,%1,%2,%3}, {%4,%5,%6,%7}, {%8,%9}, {%0,%1,%2,%3};"
        : "+f"(c[0]), "+f"(c[1]), "+f"(c[2]), "+f"(c[3])
        : "r"(a[0]), "r"(a[1]), "r"(a[2]), "r"(a[3]), "r"(b0), "r"(b1));
}
__device__ __forceinline__ void hilo(float v, __nv_bfloat16& h, __nv_bfloat16& l) {
    h = __float2bfloat16(v);
    l = __float2bfloat16(v - __bfloat162float(h));
}
__device__ __forceinline__ void cp_a8(uint32_t s, const void* g) {
    asm volatile("cp.async.ca.shared.global [%0], [%1], 8;" :: "r"(s), "l"(g) : "memory");
}
__device__ __forceinline__ void cp_a16(uint32_t s, const void* g) {
    asm volatile("cp.async.cg.shared.global [%0], [%1], 16;" :: "r"(s), "l"(g) : "memory");
}
#define CP_COMMIT()  asm volatile("cp.async.commit_group;" ::: "memory")
#define CP_WAIT(n)   asm volatile("cp.async.wait_group %0;" :: "n"(n) : "memory")

// ---------------------------------------------------------------------------
// K0: pre-split weights to bf16 hi/lo (98304 ids: 65536 W + 32768 F).
// ---------------------------------------------------------------------------
__global__ __launch_bounds__(256)
void k0_prep(const float* __restrict__ wf, const float* __restrict__ wh,
             const float* __restrict__ wfgh)
{
    const int id = blockIdx.x * 256 + threadIdx.x;
    if (id < 512 * 128) {
        const int k = id >> 7, n = id & 127;
        const float v = (n < NIC) ? wf[k * NIC + n] : wh[k * NIC + (n - NIC)];
        __nv_bfloat16 h, l; hilo(v, h, l);
        d_WH[id] = h; d_WL[id] = l;
    } else {
        const int id2 = id - 512 * 128;
        __nv_bfloat16 h, l; hilo(wfgh[id2], h, l);
        d_FH[id2] = h; d_FL[id2] = l;
    }
}

// ---------------------------------------------------------------------------
// K1 v6: CTA tile 64(M) x 128(N) — grid 1024 -> wave quantization 1.2%
// (vs 15.6% at 128x128/grid 512). BK=64, double-buffered, one sync/chunk.
// 16 warps = 2 M-warps (32 rows) x 8 N-warps (16 cols). acc 16 regs.
// Dynamic smem 111616:
//   buf0 0 / buf1 53248: AH 0(9216) | AL 9216 | BH 18432(17408) | BL 35840
//   red 106496 (64x8x2 f32) | gbuf 110592 (256 f32)
// ---------------------------------------------------------------------------
#define K1_SMEM 111616
#define K1_BUF  53248
#define A_STR 72      // 64 + 8 pad (bf16 elems)
#define B1_STR 136

__global__ __launch_bounds__(512, 1)
void k1_mma(const float* __restrict__ x,
            const float* __restrict__ gamma_f, const float* __restrict__ beta_f,
            const float* __restrict__ gamma_h, const float* __restrict__ beta_h)
{
    extern __shared__ char sm[];
    const uint32_t su = smem_u32(sm);
    const int AH = 0, AL = 9216, BH = 18432, BL = 35840;
    float (*red)[8][2] = reinterpret_cast<float (*)[8][2]>(sm + 106496);
    float* gbuf        = reinterpret_cast<float*>(sm + 110592);

    const int tid  = threadIdx.x;
    const int wid  = tid >> 5;
    const int lane = tid & 31;
    const int wn   = wid & 7;        // N warp-block (16 cols)
    const int wm2  = wid >> 3;       // M warp-block (32 rows)
    const int row0 = blockIdx.x * 64;

    if (tid < 64) {
        gbuf[tid]       = gamma_f[tid];
        gbuf[64 + tid]  = beta_f[tid];
        gbuf[128 + tid] = gamma_h[tid];
        gbuf[192 + tid] = beta_h[tid];
    }

    float acc[2][2][4];              // [mi][ns][quad]
#pragma unroll
    for (int mi = 0; mi < 2; mi++)
#pragma unroll
        for (int ns = 0; ns < 2; ns++)
#pragma unroll
            for (int q = 0; q < 4; q++) acc[mi][ns][q] = 0.0f;

    float4 pa[2];

    // ---- prolog: A(0) regs + B(0) cp.async into buf0 ----
#pragma unroll
    for (int it = 0; it < 2; it++) {
        const int f4 = tid + it * 512;           // 0..1023 (64 rows x 16 f4)
        const int m  = f4 >> 4, kc = (f4 & 15) * 4;
        pa[it] = *reinterpret_cast<const float4*>(x + (size_t)(row0 + m) * NC + kc);
    }
#pragma unroll
    for (int it = 0; it < 4; it++) {
        const int f  = tid + it * 512;           // 0..2047
        const int k  = f >> 5, nc = (f & 31) * 4;   // k 0..63
        cp_a8(su + BH + (k * B1_STR + nc) * 2, d_WH + k * 128 + nc);
        cp_a8(su + BL + (k * B1_STR + nc) * 2, d_WL + k * 128 + nc);
    }
    CP_COMMIT();

    for (int c = 0; c < 8; c++) {
        const int bo = (c & 1) * K1_BUF;

        // ---- STS A(c) with hi/lo convert ----
#pragma unroll
        for (int it = 0; it < 2; it++) {
            const int f4 = tid + it * 512;
            const int m  = f4 >> 4, kc = (f4 & 15) * 4;
            union { __nv_bfloat16 e[4]; uint2 u; } hh, ll;
            hilo(pa[it].x, hh.e[0], ll.e[0]);
            hilo(pa[it].y, hh.e[1], ll.e[1]);
            hilo(pa[it].z, hh.e[2], ll.e[2]);
            hilo(pa[it].w, hh.e[3], ll.e[3]);
            *reinterpret_cast<uint2*>(sm + bo + AH + (m * A_STR + kc) * 2) = hh.u;
            *reinterpret_cast<uint2*>(sm + bo + AL + (m * A_STR + kc) * 2) = ll.u;
        }
        CP_WAIT(0);          // B(c) landed
        __syncthreads();     // buf[c&1] visible; all warps done mma(c-1)

        if (c < 7) {         // prefetch chunk c+1 into the other buffer
            const int nbo = ((c + 1) & 1) * K1_BUF;
#pragma unroll
            for (int it = 0; it < 2; it++) {
                const int f4 = tid + it * 512;
                const int m  = f4 >> 4, kc = (f4 & 15) * 4;
                pa[it] = *reinterpret_cast<const float4*>(
                    x + (size_t)(row0 + m) * NC + (c + 1) * 64 + kc);
            }
#pragma unroll
            for (int it = 0; it < 4; it++) {
                const int f  = tid + it * 512;
                const int k  = f >> 5, nc = (f & 31) * 4;
                cp_a8(su + nbo + BH + (k * B1_STR + nc) * 2,
                      d_WH + ((c + 1) * 64 + k) * 128 + nc);
                cp_a8(su + nbo + BL + (k * B1_STR + nc) * 2,
                      d_WL + ((c + 1) * 64 + k) * 128 + nc);
            }
            CP_COMMIT();
        }

        // ---- tensor math on buf[c&1], K=64 ----
#pragma unroll
        for (int ks = 0; ks < 64; ks += 16) {
            uint32_t ah[2][4], al_[2][4];
#pragma unroll
            for (int mi = 0; mi < 2; mi++) {
                const uint32_t off =
                    ((wm2 * 32 + mi * 16 + (lane & 15)) * A_STR + ks + (lane >> 4) * 8) * 2;
                ldsm4(ah[mi],  su + bo + AH + off);
                ldsm4(al_[mi], su + bo + AL + off);
            }
            uint32_t bh[4], bl[4];
            {
                const uint32_t off =
                    ((ks + (lane & 15)) * B1_STR + wn * 16 + (lane >> 4) * 8) * 2;
                ldsm4t(bh, su + bo + BH + off);
                ldsm4t(bl, su + bo + BL + off);
            }
#pragma unroll
            for (int mi = 0; mi < 2; mi++)
#pragma unroll
                for (int ns = 0; ns < 2; ns++) {
                    mma16816(acc[mi][ns], ah[mi],  bh[2 * ns], bh[2 * ns + 1]);
                    mma16816(acc[mi][ns], ah[mi],  bl[2 * ns], bl[2 * ns + 1]);
                    mma16816(acc[mi][ns], al_[mi], bh[2 * ns], bh[2 * ns + 1]);
                }
        }
        // single sync per chunk: next STS targets the other buffer.
    }

    // ---- LN reduction direct from registers ----
#pragma unroll
    for (int mi = 0; mi < 2; mi++)
#pragma unroll
        for (int half = 0; half < 2; half++) {
            float s = 0.f, ss = 0.f;
#pragma unroll
            for (int ns = 0; ns < 2; ns++) {
                const float v0 = acc[mi][ns][half * 2];
                const float v1 = acc[mi][ns][half * 2 + 1];
                s += v0 + v1; ss += v0 * v0 + v1 * v1;
            }
#pragma unroll
            for (int o = 1; o < 4; o <<= 1) {
                s  += __shfl_xor_sync(0xffffffffu, s,  o);
                ss += __shfl_xor_sync(0xffffffffu, ss, o);
            }
            if ((lane & 3) == 0) {
                const int r = wm2 * 32 + mi * 16 + (lane >> 2) + half * 8;
                red[r][wn][0] = s;
                red[r][wn][1] = ss;
            }
        }
    __syncthreads();

    // ---- apply: combine 4 N-warps per 64-half, write d_G / d_Hs ----
    const int sel  = wn >> 2;             // 0 = f-half, 1 = h-half
    const int base = sel * 4;
    float* dstB = sel ? d_Hs : d_G;
#pragma unroll
    for (int mi = 0; mi < 2; mi++)
#pragma unroll
        for (int half = 0; half < 2; half++) {
            const int r  = wm2 * 32 + mi * 16 + (lane >> 2) + half * 8;
            const float S  = red[r][base][0] + red[r][base + 1][0] +
                             red[r][base + 2][0] + red[r][base + 3][0];
            const float SS = red[r][base][1] + red[r][base + 1][1] +
                             red[r][base + 2][1] + red[r][base + 3][1];
            const float mean = S * (1.0f / NIC);
            const float inv  = rsqrtf(SS * (1.0f / NIC) - mean * mean + LN_EPS);
            float* dst = dstB + (size_t)(row0 + r) * NIC;
#pragma unroll
            for (int ns = 0; ns < 2; ns++) {
                const int col = (wn & 3) * 16 + ns * 8 + (lane & 3) * 2;
                const float g0 = gbuf[sel * 128 + col];
                const float g1 = gbuf[sel * 128 + col + 1];
                const float b0 = gbuf[sel * 128 + 64 + col];
                const float b1 = gbuf[sel * 128 + 64 + col + 1];
                float2 o;
                o.x = (acc[mi][ns][half * 2]     - mean) * inv * g0 + b0;
                o.y = (acc[mi][ns][half * 2 + 1] - mean) * inv * g1 + b1;
                *reinterpret_cast<float2*>(dst + col) = o;
            }
        }
}

// ---------------------------------------------------------------------------
// K2 v2: 1024 threads, 4 h per thread (R13, good).
// ---------------------------------------------------------------------------
__global__ __launch_bounds__(1024)
void k2_softmax()
{
    __shared__ float red[16][64];
    const int tid = threadIdx.x;
    const int b   = blockIdx.x >> 6;
    const int w   = blockIdx.x & 63;
    const int i   = tid & 63;
    const int q   = tid >> 6;        // 0..15
    const int h0  = q * 4;

    float l[4];
#pragma unroll
    for (int hh = 0; hh < 4; hh++) {
        const int h = h0 + hh;
        const float gw = d_G[((size_t)((b * NH + w) * NW + h)) * NIC + i];
        const float gc = d_G[((size_t)((b * NH + h) * NW + w)) * NIC + i];
        l[hh] = gw * gc;
    }
    float m = fmaxf(fmaxf(l[0], l[1]), fmaxf(l[2], l[3]));
    red[q][i] = m;
    __syncthreads();
    float M = red[0][i];
#pragma unroll
    for (int p = 1; p < 16; p++) M = fmaxf(M, red[p][i]);
    __syncthreads();

    float s = 0.0f;
#pragma unroll
    for (int hh = 0; hh < 4; hh++) {
        const float e = __expf(l[hh] - M);
        l[hh] = e;
        s += e;
    }
    red[q][i] = s;
    __syncthreads();
    float S = red[0][i];
#pragma unroll
    for (int p = 1; p < 16; p++) S += red[p][i];
    const float rinv = 1.0f / S;

#pragma unroll
    for (int hh = 0; hh < 4; hh++) {
        const int h = h0 + hh;
        const size_t o = ((size_t)((b * NH + h) * NW + w)) * NIC + i;
        const float v = l[hh] * rinv * d_Hs[o];
        __nv_bfloat16 ph, pl; hilo(v, ph, pl);
        d_Phi[o] = ph;
        d_Plo[o] = pl;
    }
}

// ---------------------------------------------------------------------------
// K3 v6 (R14, good): PERSISTENT grid 148, B-resident, cp.async A
// double-buffer + smem-staged x residual.
// ---------------------------------------------------------------------------
#define K3_SMEM 228352
#define K3_GRID 148
#define K3_NT   (NROWS / 32)     // 2048 tiles
#define A3_STR 88
#define B3_STR 520
#define X_STR  520

__global__ __launch_bounds__(512, 1)
void k3_mma(const float* __restrict__ gamma, const float* __restrict__ beta,
            const float* __restrict__ scale,
            const float* __restrict__ x, float* __restrict__ out)
{
    extern __shared__ char sm[];
    const uint32_t su = smem_u32(sm);
    const int ABUF = 11264;
    const int BH = 22528, BL = 89088, XS = 155648;
    float (*red)[8][2] = reinterpret_cast<float (*)[8][2]>(sm + 222208);
    float* gbuf        = reinterpret_cast<float*>(sm + 224256);
    float* xsf         = reinterpret_cast<float*>(sm + XS);

    const int tid  = threadIdx.x;
    const int wid  = tid >> 5;
    const int lane = tid & 31;
    const int wn   = wid & 7;
    const int wm2  = wid >> 3;
    const float sc = scale[0];

    const int am = tid >> 4;
    const int ak = (tid & 15) * 4;

    if (tid < 128) {
        *reinterpret_cast<float4*>(gbuf + tid * 4) =
            *reinterpret_cast<const float4*>(gamma + tid * 4);
        *reinterpret_cast<float4*>(gbuf + 512 + tid * 4) =
            *reinterpret_cast<const float4*>(beta + tid * 4);
    }
#pragma unroll
    for (int it = 0; it < 8; it++) {
        const int f  = tid + it * 512;
        const int k  = f >> 6;
        const int n8 = (f & 63) * 8;
        cp_a16(su + BH + (k * B3_STR + n8) * 2, d_FH + k * NC + n8);
        cp_a16(su + BL + (k * B3_STR + n8) * 2, d_FL + k * NC + n8);
    }
    {
        const size_t go = (size_t)(blockIdx.x * 32 + am) * NIC + ak;
        cp_a8(su + (am * A3_STR + ak) * 2, d_Phi + go);
        cp_a8(su + 5632 + (am * A3_STR + ak) * 2, d_Plo + go);
    }
    CP_COMMIT();

    int itc = 0;
    for (int t = blockIdx.x; t < K3_NT; t += K3_GRID, itc++) {
        const int row0 = t * 32;
        const bool hasnext = (t + K3_GRID) < K3_NT;

        CP_WAIT(0);
        __syncthreads();

#pragma unroll
        for (int it = 0; it < 8; it++) {
            const int f  = tid + it * 512;
            const int r  = f >> 7;
            const int c4 = (f & 127) * 4;
            cp_a16(su + XS + (r * X_STR + c4) * 4,
                   x + (size_t)(row0 + r) * NC + c4);
        }
        CP_COMMIT();

        if (hasnext) {
            const int nb = ((itc + 1) & 1) * ABUF;
            const size_t go = (size_t)((t + K3_GRID) * 32 + am) * NIC + ak;
            cp_a8(su + nb + (am * A3_STR + ak) * 2, d_Phi + go);
            cp_a8(su + nb + 5632 + (am * A3_STR + ak) * 2, d_Plo + go);
            CP_COMMIT();
        }

        const int AHo = (itc & 1) * ABUF;
        const int ALo = AHo + 5632;

        float acc[8][4];
#pragma unroll
        for (int ni = 0; ni < 8; ni++)
#pragma unroll
            for (int q = 0; q < 4; q++) acc[ni][q] = 0.0f;

#pragma unroll
        for (int ks = 0; ks < 64; ks += 16) {
            uint32_t ah[4], al_[4];
            {
                const uint32_t off =
                    ((wm2 * 16 + (lane & 15)) * A3_STR + ks + (lane >> 4) * 8) * 2;
                ldsm4(ah,  su + AHo + off);
                ldsm4(al_, su + ALo + off);
            }
            uint32_t bh[4][4], bl[4][4];
#pragma unroll
            for (int p = 0; p < 4; p++) {
                const uint32_t off =
                    ((ks + (lane & 15)) * B3_STR + wn * 64 + p * 16 + (lane >> 4) * 8) * 2;
                ldsm4t(bh[p], su + BH + off);
                ldsm4t(bl[p], su + BL + off);
            }
#pragma unroll
            for (int p = 0; p < 4; p++)
#pragma unroll
                for (int ns = 0; ns < 2; ns++) {
                    const int ni = p * 2 + ns;
                    mma16816(acc[ni], ah,  bh[p][2 * ns], bh[p][2 * ns + 1]);
                    mma16816(acc[ni], ah,  bl[p][2 * ns], bl[p][2 * ns + 1]);
                    mma16816(acc[ni], al_, bh[p][2 * ns], bh[p][2 * ns + 1]);
                }
        }

#pragma unroll
        for (int half = 0; half < 2; half++) {
            float s = 0.f, ss = 0.f;
#pragma unroll
            for (int ni = 0; ni < 8; ni++) {
                const float v0 = acc[ni][half * 2];
                const float v1 = acc[ni][half * 2 + 1];
                s += v0 + v1; ss += v0 * v0 + v1 * v1;
            }
#pragma unroll
            for (int o = 1; o < 4; o <<= 1) {
                s  += __shfl_xor_sync(0xffffffffu, s,  o);
                ss += __shfl_xor_sync(0xffffffffu, ss, o);
            }
            if ((lane & 3) == 0) {
                const int r = wm2 * 16 + (lane >> 2) + half * 8;
                red[r][wn][0] = s;
                red[r][wn][1] = ss;
            }
        }

        if (hasnext) { CP_WAIT(1); } else { CP_WAIT(0); }
        __syncthreads();

        float mean[2], inv[2];
#pragma unroll
        for (int half = 0; half < 2; half++) {
            const int r = wm2 * 16 + (lane >> 2) + half * 8;
            float S = 0.f, SS = 0.f;
#pragma unroll
            for (int w8 = 0; w8 < 8; w8++) { S += red[r][w8][0]; SS += red[r][w8][1]; }
            const float m = S * (1.0f / NC);
            mean[half] = m;
            inv[half]  = rsqrtf(SS * (1.0f / NC) - m * m + LN_EPS);
        }

#pragma unroll
        for (int ni = 0; ni < 8; ni++) {
            const int col = wn * 64 + ni * 8 + (lane & 3) * 2;
            const float g0 = gbuf[col],       g1 = gbuf[col + 1];
            const float b0 = gbuf[512 + col], b1 = gbuf[512 + col + 1];
#pragma unroll
            for (int half = 0; half < 2; half++) {
                const int rl = wm2 * 16 + (lane >> 2) + half * 8;
                const float2 x2 = *reinterpret_cast<const float2*>(
                    xsf + rl * X_STR + col);
                float2 o;
                o.x = x2.x + ((acc[ni][half * 2]     - mean[half]) * inv[half] * g0 + b0) * sc;
                o.y = x2.y + ((acc[ni][half * 2 + 1] - mean[half]) * inv[half] * g1 + b1) * sc;
                *reinterpret_cast<float2*>(out + (size_t)(row0 + rl) * NC + col) = o;
            }
        }
    }
}

// ---------------------------------------------------------------------------
// Launch. Inputs: 0:x 1:w_f 2:w_h 3:w_fgh 4:gamma_f 5:beta_f 6:gamma_h
// 7:beta_h 8:gamma_fgh 9:beta_fgh 10:scale
// ---------------------------------------------------------------------------
extern "C" void kernel_launch(void* const* d_in, const int* in_sizes, int n_in,
                              void* d_out, int out_size)
{
    (void)in_sizes; (void)n_in; (void)out_size;
    const float* x         = (const float*)d_in[0];
    const float* w_f       = (const float*)d_in[1];
    const float* w_h       = (const float*)d_in[2];
    const float* w_fgh     = (const float*)d_in[3];
    const float* gamma_f   = (const float*)d_in[4];
    const float* beta_f    = (const float*)d_in[5];
    const float* gamma_h   = (const float*)d_in[6];
    const float* beta_h    = (const float*)d_in[7];
    const float* gamma_fgh = (const float*)d_in[8];
    const float* beta_fgh  = (const float*)d_in[9];
    const float* scale     = (const float*)d_in[10];
    float* out             = (float*)d_out;

    cudaFuncSetAttribute(k1_mma, cudaFuncAttributeMaxDynamicSharedMemorySize, K1_SMEM);
    cudaFuncSetAttribute(k3_mma, cudaFuncAttributeMaxDynamicSharedMemorySize, K3_SMEM);

    k0_prep<<<384, 256>>>(w_f, w_h, w_fgh);
    k1_mma<<<NROWS / 64, 512, K1_SMEM>>>(x, gamma_f, beta_f, gamma_h, beta_h);
    k2_softmax<<<NB * NW, 1024>>>();
    k3_mma<<<K3_GRID, 512, K3_SMEM>>>(gamma_fgh, beta_fgh, scale, x, out);
}

// round 16
// speedup vs baseline: 1.1110x; 1.1110x over previous
#include <cuda_runtime.h>
#include <cuda_bf16.h>
#include <cstdint>
#include <cstddef>

// ---------------------------------------------------------------------------
// Problem constants
// ---------------------------------------------------------------------------
#define NB   16
#define NH   64
#define NW   64
#define NC   512
#define NIC  64
#define NROWS (NB*NH*NW)          // 65536
#define LN_EPS 1e-3f

// Scratch (device globals = sanctioned no-alloc scratch)
__device__ float d_G [(size_t)NROWS * NIC];
__device__ float d_Hs[(size_t)NROWS * NIC];
__device__ __nv_bfloat16 d_Phi[(size_t)NROWS * NIC];
__device__ __nv_bfloat16 d_Plo[(size_t)NROWS * NIC];
// Pre-split weights: [wf|wh] as [512][128], w_fgh as [64][512]
__device__ __nv_bfloat16 d_WH[512 * 128];
__device__ __nv_bfloat16 d_WL[512 * 128];
__device__ __nv_bfloat16 d_FH[64 * 512];
__device__ __nv_bfloat16 d_FL[64 * 512];

// ---------------------------------------------------------------------------
// Helpers (sm_80-family tensor path: mma.sync + ldmatrix + cp.async)
// ---------------------------------------------------------------------------
__device__ __forceinline__ uint32_t smem_u32(const void* p) {
    uint32_t a;
    asm("{ .reg .u64 t; cvta.to.shared.u64 t, %1; cvt.u32.u64 %0, t; }"
        : "=r"(a) : "l"(p));
    return a;
}
__device__ __forceinline__ void ldsm4(uint32_t r[4], uint32_t a) {
    asm volatile("ldmatrix.sync.aligned.m8n8.x4.shared.b16 {%0,%1,%2,%3}, [%4];"
                 : "=r"(r[0]), "=r"(r[1]), "=r"(r[2]), "=r"(r[3]) : "r"(a));
}
__device__ __forceinline__ void ldsm4t(uint32_t r[4], uint32_t a) {
    asm volatile("ldmatrix.sync.aligned.m8n8.x4.trans.shared.b16 {%0,%1,%2,%3}, [%4];"
                 : "=r"(r[0]), "=r"(r[1]), "=r"(r[2]), "=r"(r[3]) : "r"(a));
}
__device__ __forceinline__ void mma16816(float c[4], const uint32_t a[4],
                                         uint32_t b0, uint32_t b1) {
    asm volatile(
        "mma.sync.aligned.m16n8k16.row.col.f32.bf16.bf16.f32 "
        "{%0,%1,%2,%3}, {%4,%5,%6,%7}, {%8,%9}, {%0,%1,%2,%3};"
        : "+f"(c[0]), "+f"(c[1]), "+f"(c[2]), "+f"(c[3])
        : "r"(a[0]), "r"(a[1]), "r"(a[2]), "r"(a[3]), "r"(b0), "r"(b1));
}
__device__ __forceinline__ void hilo(float v, __nv_bfloat16& h, __nv_bfloat16& l) {
    h = __float2bfloat16(v);
    l = __float2bfloat16(v - __bfloat162float(h));
}
__device__ __forceinline__ void cp_a8(uint32_t s, const void* g) {
    asm volatile("cp.async.ca.shared.global [%0], [%1], 8;" :: "r"(s), "l"(g) : "memory");
}
__device__ __forceinline__ void cp_a16(uint32_t s, const void* g) {
    asm volatile("cp.async.cg.shared.global [%0], [%1], 16;" :: "r"(s), "l"(g) : "memory");
}
#define CP_COMMIT()  asm volatile("cp.async.commit_group;" ::: "memory")
#define CP_WAIT(n)   asm volatile("cp.async.wait_group %0;" :: "n"(n) : "memory")

// ---------------------------------------------------------------------------
// K0: pre-split weights to bf16 hi/lo (98304 ids: 65536 W + 32768 F).
// ---------------------------------------------------------------------------
__global__ __launch_bounds__(256)
void k0_prep(const float* __restrict__ wf, const float* __restrict__ wh,
             const float* __restrict__ wfgh)
{
    const int id = blockIdx.x * 256 + threadIdx.x;
    if (id < 512 * 128) {
        const int k = id >> 7, n = id & 127;
        const float v = (n < NIC) ? wf[k * NIC + n] : wh[k * NIC + (n - NIC)];
        __nv_bfloat16 h, l; hilo(v, h, l);
        d_WH[id] = h; d_WL[id] = l;
    } else {
        const int id2 = id - 512 * 128;
        __nv_bfloat16 h, l; hilo(wfgh[id2], h, l);
        d_FH[id2] = h; d_FL[id2] = l;
    }
}

// ---------------------------------------------------------------------------
// K1 v7: CTA 64(M) x 128(N), 256 threads (8 warps = 2M x 4N, warp tile
// 32x32), BK=32, double-buffered, one sync/chunk. Natural regs (~100) ->
// 2 CTAs/SM WITHOUT a reg cap; smem 58368 allows up to 3. Independent CTA
// barriers decorrelate chunk-boundary stalls (the R9-R15 bottleneck).
// smem: buf0 0 / buf1 27648, each: AH 0(5120) | AL 5120 | BH 10240(8704)
//       | BL 18944 ; red 55296 (64x4x2 f32) | gbuf 57344 (256 f32)
// ---------------------------------------------------------------------------
#define K1_SMEM 58368
#define K1_BUF  27648
#define A_STR 40
#define B1_STR 136

__global__ __launch_bounds__(256, 2)
void k1_mma(const float* __restrict__ x,
            const float* __restrict__ gamma_f, const float* __restrict__ beta_f,
            const float* __restrict__ gamma_h, const float* __restrict__ beta_h)
{
    extern __shared__ char sm[];
    const uint32_t su = smem_u32(sm);
    const int AH = 0, AL = 5120, BH = 10240, BL = 18944;
    float (*red)[4][2] = reinterpret_cast<float (*)[4][2]>(sm + 55296);
    float* gbuf        = reinterpret_cast<float*>(sm + 57344);

    const int tid  = threadIdx.x;
    const int wid  = tid >> 5;
    const int lane = tid & 31;
    const int wm   = wid & 1;        // M warp-block (32 rows)
    const int wn   = wid >> 1;       // N warp-block (32 cols), 0..3
    const int row0 = blockIdx.x * 64;

    if (tid < 64) {
        gbuf[tid]       = gamma_f[tid];
        gbuf[64 + tid]  = beta_f[tid];
        gbuf[128 + tid] = gamma_h[tid];
        gbuf[192 + tid] = beta_h[tid];
    }

    float acc[2][4][4];
#pragma unroll
    for (int mi = 0; mi < 2; mi++)
#pragma unroll
        for (int ni = 0; ni < 4; ni++)
#pragma unroll
            for (int q = 0; q < 4; q++) acc[mi][ni][q] = 0.0f;

    float4 pa[2];

    // ---- prolog: A(0) regs + B(0) cp.async into buf0 ----
#pragma unroll
    for (int it = 0; it < 2; it++) {
        const int f4 = tid + it * 256;           // 0..511 (64 rows x 8 f4)
        const int m  = f4 >> 3, kc = (f4 & 7) * 4;
        pa[it] = *reinterpret_cast<const float4*>(x + (size_t)(row0 + m) * NC + kc);
    }
#pragma unroll
    for (int it = 0; it < 4; it++) {
        const int f  = tid + it * 256;           // 0..1023
        const int k  = f >> 5, nc = (f & 31) * 4;   // k 0..31
        cp_a8(su + BH + (k * B1_STR + nc) * 2, d_WH + k * 128 + nc);
        cp_a8(su + BL + (k * B1_STR + nc) * 2, d_WL + k * 128 + nc);
    }
    CP_COMMIT();

    for (int c = 0; c < 16; c++) {
        const int bo = (c & 1) * K1_BUF;

        // ---- STS A(c) with hi/lo convert ----
#pragma unroll
        for (int it = 0; it < 2; it++) {
            const int f4 = tid + it * 256;
            const int m  = f4 >> 3, kc = (f4 & 7) * 4;
            union { __nv_bfloat16 e[4]; uint2 u; } hh, ll;
            hilo(pa[it].x, hh.e[0], ll.e[0]);
            hilo(pa[it].y, hh.e[1], ll.e[1]);
            hilo(pa[it].z, hh.e[2], ll.e[2]);
            hilo(pa[it].w, hh.e[3], ll.e[3]);
            *reinterpret_cast<uint2*>(sm + bo + AH + (m * A_STR + kc) * 2) = hh.u;
            *reinterpret_cast<uint2*>(sm + bo + AL + (m * A_STR + kc) * 2) = ll.u;
        }
        CP_WAIT(0);          // B(c) landed
        __syncthreads();     // buf[c&1] visible; all warps done mma(c-1)

        if (c < 15) {        // prefetch chunk c+1 into the other buffer
            const int nbo = ((c + 1) & 1) * K1_BUF;
#pragma unroll
            for (int it = 0; it < 2; it++) {
                const int f4 = tid + it * 256;
                const int m  = f4 >> 3, kc = (f4 & 7) * 4;
                pa[it] = *reinterpret_cast<const float4*>(
                    x + (size_t)(row0 + m) * NC + (c + 1) * 32 + kc);
            }
#pragma unroll
            for (int it = 0; it < 4; it++) {
                const int f  = tid + it * 256;
                const int k  = f >> 5, nc = (f & 31) * 4;
                cp_a8(su + nbo + BH + (k * B1_STR + nc) * 2,
                      d_WH + ((c + 1) * 32 + k) * 128 + nc);
                cp_a8(su + nbo + BL + (k * B1_STR + nc) * 2,
                      d_WL + ((c + 1) * 32 + k) * 128 + nc);
            }
            CP_COMMIT();
        }

        // ---- tensor math on buf[c&1], K=32 ----
#pragma unroll
        for (int ks = 0; ks < 32; ks += 16) {
            uint32_t ah[2][4], al_[2][4];
#pragma unroll
            for (int mi = 0; mi < 2; mi++) {
                const uint32_t off =
                    ((wm * 32 + mi * 16 + (lane & 15)) * A_STR + ks + (lane >> 4) * 8) * 2;
                ldsm4(ah[mi],  su + bo + AH + off);
                ldsm4(al_[mi], su + bo + AL + off);
            }
            uint32_t bh[2][4], bl[2][4];
#pragma unroll
            for (int p = 0; p < 2; p++) {
                const uint32_t off =
                    ((ks + (lane & 15)) * B1_STR + wn * 32 + p * 16 + (lane >> 4) * 8) * 2;
                ldsm4t(bh[p], su + bo + BH + off);
                ldsm4t(bl[p], su + bo + BL + off);
            }
#pragma unroll
            for (int mi = 0; mi < 2; mi++)
#pragma unroll
                for (int p = 0; p < 2; p++)
#pragma unroll
                    for (int ns = 0; ns < 2; ns++) {
                        const int ni = p * 2 + ns;
                        mma16816(acc[mi][ni], ah[mi],  bh[p][2 * ns], bh[p][2 * ns + 1]);
                        mma16816(acc[mi][ni], ah[mi],  bl[p][2 * ns], bl[p][2 * ns + 1]);
                        mma16816(acc[mi][ni], al_[mi], bh[p][2 * ns], bh[p][2 * ns + 1]);
                    }
        }
        // single sync per chunk: next STS targets the other buffer.
    }

    // ---- LN reduction direct from registers ----
#pragma unroll
    for (int mi = 0; mi < 2; mi++)
#pragma unroll
        for (int half = 0; half < 2; half++) {
            float s = 0.f, ss = 0.f;
#pragma unroll
            for (int ni = 0; ni < 4; ni++) {
                const float v0 = acc[mi][ni][half * 2];
                const float v1 = acc[mi][ni][half * 2 + 1];
                s += v0 + v1; ss += v0 * v0 + v1 * v1;
            }
#pragma unroll
            for (int o = 1; o < 4; o <<= 1) {
                s  += __shfl_xor_sync(0xffffffffu, s,  o);
                ss += __shfl_xor_sync(0xffffffffu, ss, o);
            }
            if ((lane & 3) == 0) {
                const int r = wm * 32 + mi * 16 + (lane >> 2) + half * 8;
                red[r][wn][0] = s;
                red[r][wn][1] = ss;
            }
        }
    __syncthreads();

    // ---- apply: combine 2 N-warps per 64-half, write d_G / d_Hs ----
    const int sel  = wn >> 1;            // 0 = f-half, 1 = h-half
    const int base = sel * 2;
    float* dstB = sel ? d_Hs : d_G;
#pragma unroll
    for (int mi = 0; mi < 2; mi++)
#pragma unroll
        for (int half = 0; half < 2; half++) {
            const int r  = wm * 32 + mi * 16 + (lane >> 2) + half * 8;
            const float S  = red[r][base][0] + red[r][base + 1][0];
            const float SS = red[r][base][1] + red[r][base + 1][1];
            const float mean = S * (1.0f / NIC);
            const float inv  = rsqrtf(SS * (1.0f / NIC) - mean * mean + LN_EPS);
            float* dst = dstB + (size_t)(row0 + r) * NIC;
#pragma unroll
            for (int ni = 0; ni < 4; ni++) {
                const int col = (wn & 1) * 32 + ni * 8 + (lane & 3) * 2;
                const float g0 = gbuf[sel * 128 + col];
                const float g1 = gbuf[sel * 128 + col + 1];
                const float b0 = gbuf[sel * 128 + 64 + col];
                const float b1 = gbuf[sel * 128 + 64 + col + 1];
                float2 o;
                o.x = (acc[mi][ni][half * 2]     - mean) * inv * g0 + b0;
                o.y = (acc[mi][ni][half * 2 + 1] - mean) * inv * g1 + b1;
                *reinterpret_cast<float2*>(dst + col) = o;
            }
        }
}

// ---------------------------------------------------------------------------
// K2 v2: 1024 threads, 4 h per thread (R13, good).
// ---------------------------------------------------------------------------
__global__ __launch_bounds__(1024)
void k2_softmax()
{
    __shared__ float red[16][64];
    const int tid = threadIdx.x;
    const int b   = blockIdx.x >> 6;
    const int w   = blockIdx.x & 63;
    const int i   = tid & 63;
    const int q   = tid >> 6;        // 0..15
    const int h0  = q * 4;

    float l[4];
#pragma unroll
    for (int hh = 0; hh < 4; hh++) {
        const int h = h0 + hh;
        const float gw = d_G[((size_t)((b * NH + w) * NW + h)) * NIC + i];
        const float gc = d_G[((size_t)((b * NH + h) * NW + w)) * NIC + i];
        l[hh] = gw * gc;
    }
    float m = fmaxf(fmaxf(l[0], l[1]), fmaxf(l[2], l[3]));
    red[q][i] = m;
    __syncthreads();
    float M = red[0][i];
#pragma unroll
    for (int p = 1; p < 16; p++) M = fmaxf(M, red[p][i]);
    __syncthreads();

    float s = 0.0f;
#pragma unroll
    for (int hh = 0; hh < 4; hh++) {
        const float e = __expf(l[hh] - M);
        l[hh] = e;
        s += e;
    }
    red[q][i] = s;
    __syncthreads();
    float S = red[0][i];
#pragma unroll
    for (int p = 1; p < 16; p++) S += red[p][i];
    const float rinv = 1.0f / S;

#pragma unroll
    for (int hh = 0; hh < 4; hh++) {
        const int h = h0 + hh;
        const size_t o = ((size_t)((b * NH + h) * NW + w)) * NIC + i;
        const float v = l[hh] * rinv * d_Hs[o];
        __nv_bfloat16 ph, pl; hilo(v, ph, pl);
        d_Phi[o] = ph;
        d_Plo[o] = pl;
    }
}

// ---------------------------------------------------------------------------
// K3 v6 (R14, good): PERSISTENT grid 148, B-resident, cp.async A
// double-buffer + smem-staged x residual.
// ---------------------------------------------------------------------------
#define K3_SMEM 228352
#define K3_GRID 148
#define K3_NT   (NROWS / 32)     // 2048 tiles
#define A3_STR 88
#define B3_STR 520
#define X_STR  520

__global__ __launch_bounds__(512, 1)
void k3_mma(const float* __restrict__ gamma, const float* __restrict__ beta,
            const float* __restrict__ scale,
            const float* __restrict__ x, float* __restrict__ out)
{
    extern __shared__ char sm[];
    const uint32_t su = smem_u32(sm);
    const int ABUF = 11264;
    const int BH = 22528, BL = 89088, XS = 155648;
    float (*red)[8][2] = reinterpret_cast<float (*)[8][2]>(sm + 222208);
    float* gbuf        = reinterpret_cast<float*>(sm + 224256);
    float* xsf         = reinterpret_cast<float*>(sm + XS);

    const int tid  = threadIdx.x;
    const int wid  = tid >> 5;
    const int lane = tid & 31;
    const int wn   = wid & 7;
    const int wm2  = wid >> 3;
    const float sc = scale[0];

    const int am = tid >> 4;
    const int ak = (tid & 15) * 4;

    if (tid < 128) {
        *reinterpret_cast<float4*>(gbuf + tid * 4) =
            *reinterpret_cast<const float4*>(gamma + tid * 4);
        *reinterpret_cast<float4*>(gbuf + 512 + tid * 4) =
            *reinterpret_cast<const float4*>(beta + tid * 4);
    }
#pragma unroll
    for (int it = 0; it < 8; it++) {
        const int f  = tid + it * 512;
        const int k  = f >> 6;
        const int n8 = (f & 63) * 8;
        cp_a16(su + BH + (k * B3_STR + n8) * 2, d_FH + k * NC + n8);
        cp_a16(su + BL + (k * B3_STR + n8) * 2, d_FL + k * NC + n8);
    }
    {
        const size_t go = (size_t)(blockIdx.x * 32 + am) * NIC + ak;
        cp_a8(su + (am * A3_STR + ak) * 2, d_Phi + go);
        cp_a8(su + 5632 + (am * A3_STR + ak) * 2, d_Plo + go);
    }
    CP_COMMIT();

    int itc = 0;
    for (int t = blockIdx.x; t < K3_NT; t += K3_GRID, itc++) {
        const int row0 = t * 32;
        const bool hasnext = (t + K3_GRID) < K3_NT;

        CP_WAIT(0);
        __syncthreads();

#pragma unroll
        for (int it = 0; it < 8; it++) {
            const int f  = tid + it * 512;
            const int r  = f >> 7;
            const int c4 = (f & 127) * 4;
            cp_a16(su + XS + (r * X_STR + c4) * 4,
                   x + (size_t)(row0 + r) * NC + c4);
        }
        CP_COMMIT();

        if (hasnext) {
            const int nb = ((itc + 1) & 1) * ABUF;
            const size_t go = (size_t)((t + K3_GRID) * 32 + am) * NIC + ak;
            cp_a8(su + nb + (am * A3_STR + ak) * 2, d_Phi + go);
            cp_a8(su + nb + 5632 + (am * A3_STR + ak) * 2, d_Plo + go);
            CP_COMMIT();
        }

        const int AHo = (itc & 1) * ABUF;
        const int ALo = AHo + 5632;

        float acc[8][4];
#pragma unroll
        for (int ni = 0; ni < 8; ni++)
#pragma unroll
            for (int q = 0; q < 4; q++) acc[ni][q] = 0.0f;

#pragma unroll
        for (int ks = 0; ks < 64; ks += 16) {
            uint32_t ah[4], al_[4];
            {
                const uint32_t off =
                    ((wm2 * 16 + (lane & 15)) * A3_STR + ks + (lane >> 4) * 8) * 2;
                ldsm4(ah,  su + AHo + off);
                ldsm4(al_, su + ALo + off);
            }
            uint32_t bh[4][4], bl[4][4];
#pragma unroll
            for (int p = 0; p < 4; p++) {
                const uint32_t off =
                    ((ks + (lane & 15)) * B3_STR + wn * 64 + p * 16 + (lane >> 4) * 8) * 2;
                ldsm4t(bh[p], su + BH + off);
                ldsm4t(bl[p], su + BL + off);
            }
#pragma unroll
            for (int p = 0; p < 4; p++)
#pragma unroll
                for (int ns = 0; ns < 2; ns++) {
                    const int ni = p * 2 + ns;
                    mma16816(acc[ni], ah,  bh[p][2 * ns], bh[p][2 * ns + 1]);
                    mma16816(acc[ni], ah,  bl[p][2 * ns], bl[p][2 * ns + 1]);
                    mma16816(acc[ni], al_, bh[p][2 * ns], bh[p][2 * ns + 1]);
                }
        }

#pragma unroll
        for (int half = 0; half < 2; half++) {
            float s = 0.f, ss = 0.f;
#pragma unroll
            for (int ni = 0; ni < 8; ni++) {
                const float v0 = acc[ni][half * 2];
                const float v1 = acc[ni][half * 2 + 1];
                s += v0 + v1; ss += v0 * v0 + v1 * v1;
            }
#pragma unroll
            for (int o = 1; o < 4; o <<= 1) {
                s  += __shfl_xor_sync(0xffffffffu, s,  o);
                ss += __shfl_xor_sync(0xffffffffu, ss, o);
            }
            if ((lane & 3) == 0) {
                const int r = wm2 * 16 + (lane >> 2) + half * 8;
                red[r][wn][0] = s;
                red[r][wn][1] = ss;
            }
        }

        if (hasnext) { CP_WAIT(1); } else { CP_WAIT(0); }
        __syncthreads();

        float mean[2], inv[2];
#pragma unroll
        for (int half = 0; half < 2; half++) {
            const int r = wm2 * 16 + (lane >> 2) + half * 8;
            float S = 0.f, SS = 0.f;
#pragma unroll
            for (int w8 = 0; w8 < 8; w8++) { S += red[r][w8][0]; SS += red[r][w8][1]; }
            const float m = S * (1.0f / NC);
            mean[half] = m;
            inv[half]  = rsqrtf(SS * (1.0f / NC) - m * m + LN_EPS);
        }

#pragma unroll
        for (int ni = 0; ni < 8; ni++) {
            const int col = wn * 64 + ni * 8 + (lane & 3) * 2;
            const float g0 = gbuf[col],       g1 = gbuf[col + 1];
            const float b0 = gbuf[512 + col], b1 = gbuf[512 + col + 1];
#pragma unroll
            for (int half = 0; half < 2; half++) {
                const int rl = wm2 * 16 + (lane >> 2) + half * 8;
                const float2 x2 = *reinterpret_cast<const float2*>(
                    xsf + rl * X_STR + col);
                float2 o;
                o.x = x2.x + ((acc[ni][half * 2]     - mean[half]) * inv[half] * g0 + b0) * sc;
                o.y = x2.y + ((acc[ni][half * 2 + 1] - mean[half]) * inv[half] * g1 + b1) * sc;
                *reinterpret_cast<float2*>(out + (size_t)(row0 + rl) * NC + col) = o;
            }
        }
    }
}

// ---------------------------------------------------------------------------
// Launch. Inputs: 0:x 1:w_f 2:w_h 3:w_fgh 4:gamma_f 5:beta_f 6:gamma_h
// 7:beta_h 8:gamma_fgh 9:beta_fgh 10:scale
// ---------------------------------------------------------------------------
extern "C" void kernel_launch(void* const* d_in, const int* in_sizes, int n_in,
                              void* d_out, int out_size)
{
    (void)in_sizes; (void)n_in; (void)out_size;
    const float* x         = (const float*)d_in[0];
    const float* w_f       = (const float*)d_in[1];
    const float* w_h       = (const float*)d_in[2];
    const float* w_fgh     = (const float*)d_in[3];
    const float* gamma_f   = (const float*)d_in[4];
    const float* beta_f    = (const float*)d_in[5];
    const float* gamma_h   = (const float*)d_in[6];
    const float* beta_h    = (const float*)d_in[7];
    const float* gamma_fgh = (const float*)d_in[8];
    const float* beta_fgh  = (const float*)d_in[9];
    const float* scale     = (const float*)d_in[10];
    float* out             = (float*)d_out;

    cudaFuncSetAttribute(k1_mma, cudaFuncAttributeMaxDynamicSharedMemorySize, K1_SMEM);
    cudaFuncSetAttribute(k3_mma, cudaFuncAttributeMaxDynamicSharedMemorySize, K3_SMEM);

    k0_prep<<<384, 256>>>(w_f, w_h, w_fgh);
    k1_mma<<<NROWS / 64, 256, K1_SMEM>>>(x, gamma_f, beta_f, gamma_h, beta_h);
    k2_softmax<<<NB * NW, 1024>>>();
    k3_mma<<<K3_GRID, 512, K3_SMEM>>>(gamma_fgh, beta_fgh, scale, x, out);
}